// round 16
// baseline (speedup 1.0000x reference)
#include <cuda_runtime.h>
#include <cuda_bf16.h>
#include <math.h>
#include <stdint.h>

// ---------------------------------------------------------------------------
// TrackMPNN forward, fp32. GRU via mma.sync bf16 hi/lo split over masked row
// lists. 512-thread GRU with cp.async cross-tile pipelining of both gathers.
// h stored pre-split (bf16 hi/lo) in global. m staged raw fp32 via cp.async.
// Output: concat( sigmoid(y)[N], y[N], h_out[N,64] ) as float32.
// ---------------------------------------------------------------------------

#define NH 64
#define MAXN      400000
#define MAXNEW    100000

__device__ float g_dn[MAXN];
__device__ float g_de[MAXN];
__device__ float g_mn[(size_t)MAXN * NH];
__device__ float g_me[(size_t)MAXN * NH];
__device__ __nv_bfloat16 g_h_hi[(size_t)MAXN * NH];
__device__ __nv_bfloat16 g_h_lo[(size_t)MAXN * NH];
__device__ float g_G[64 * 64];
__device__ float g_s[64];
__device__ float g_a[64], g_bsh[64];
__device__ int   g_ticket;
__device__ int   g_nlist[MAXN], g_elist[MAXN];
__device__ int   g_ncnt, g_ecnt;
__device__ __nv_bfloat16 g_wbh[4][192 * 64];
__device__ __nv_bfloat16 g_wbl[4][192 * 64];

__device__ __forceinline__ float sigmoidf_(float v) { return 1.f / (1.f + __expf(-v)); }
__device__ __forceinline__ float tanhf_(float v) {
    float t = __expf(2.f * v);
    return (t - 1.f) * (1.f / (t + 1.f));
}
__device__ __forceinline__ float bfu_(unsigned short u) {
    __nv_bfloat16 t = *reinterpret_cast<__nv_bfloat16*>(&u);
    return __bfloat162float(t);
}
// float4 -> bf16 hi[2]/lo[2] packed words
static __device__ __forceinline__ void cvt_pack(const float4& v, uint32_t* hiw, uint32_t* low) {
#pragma unroll
    for (int p2 = 0; p2 < 2; p2++) {
        float a0 = p2 ? v.z : v.x, a1 = p2 ? v.w : v.y;
        __nv_bfloat16 h0 = __float2bfloat16(a0);
        __nv_bfloat16 h1 = __float2bfloat16(a1);
        __nv_bfloat16 l0 = __float2bfloat16(a0 - __bfloat162float(h0));
        __nv_bfloat16 l1 = __float2bfloat16(a1 - __bfloat162float(h1));
        hiw[p2] = (uint32_t)*reinterpret_cast<unsigned short*>(&h0) |
                  ((uint32_t)*reinterpret_cast<unsigned short*>(&h1) << 16);
        low[p2] = (uint32_t)*reinterpret_cast<unsigned short*>(&l0) |
                  ((uint32_t)*reinterpret_cast<unsigned short*>(&l1) << 16);
    }
}

// ---------------------------------------------------------------------------
// prep: copy h_in -> split h, diag extract, weight split, Gram stats + BN.
// ---------------------------------------------------------------------------
__global__ void prep_kernel(const float* __restrict__ h_in,
                            const int* __restrict__ nrows, const int* __restrict__ ncols,
                            const float* __restrict__ nvals, int nnz_n,
                            const int* __restrict__ erows, const int* __restrict__ ecols,
                            const float* __restrict__ evals, int nnz_e,
                            const float* __restrict__ x,
                            const float* __restrict__ W1, const float* __restrict__ b1,
                            const float* __restrict__ gamma, const float* __restrict__ beta,
                            const float* __restrict__ Wi_n, const float* __restrict__ Wh_n,
                            const float* __restrict__ Wi_e, const float* __restrict__ Wh_e,
                            int N, int Nold, int Nnew) {
    __shared__ float sx[16 * 64];
    __shared__ float sG[64 * 64];
    __shared__ float sW1s[64 * 64];
    __shared__ int s_last;

    int tid = threadIdx.x;
    size_t i = (size_t)blockIdx.x * blockDim.x + tid;
    size_t stride = (size_t)gridDim.x * blockDim.x;

    if (i == 0) { g_ncnt = 0; g_ecnt = 0; }

    const float4* hin4 = reinterpret_cast<const float4*>(h_in);
    uint2* hh2 = reinterpret_cast<uint2*>(g_h_hi);
    uint2* hl2 = reinterpret_cast<uint2*>(g_h_lo);
    size_t c4 = (size_t)Nold * (NH / 4);
    for (size_t idx = i; idx < c4; idx += stride) {
        float4 v = hin4[idx];
        uint32_t hiw[2], low[2];
        cvt_pack(v, hiw, low);
        hh2[idx] = make_uint2(hiw[0], hiw[1]);
        hl2[idx] = make_uint2(low[0], low[1]);
    }
    for (size_t e = i; e < (size_t)nnz_n; e += stride) {
        int r = nrows[e];
        if (r == ncols[e]) g_dn[r] = nvals[e];
    }
    for (size_t e = i; e < (size_t)nnz_e; e += stride) {
        int r = erows[e];
        if (r == ecols[e]) g_de[r] = evals[e];
    }
    const float* wsrc[4] = {Wi_n, Wh_n, Wi_e, Wh_e};
    for (size_t w = i; w < 4 * 12288; w += stride) {
        int mat = (int)(w / 12288), off = (int)(w % 12288);
        float v = wsrc[mat][off];
        __nv_bfloat16 hi = __float2bfloat16(v);
        float res = v - __bfloat162float(hi);
        g_wbh[mat][off] = hi;
        g_wbl[mat][off] = __float2bfloat16(res);
    }

    if (blockIdx.x < 256) {
        int j = tid & 63, rg = tid >> 6;
        float gacc[16];
#pragma unroll
        for (int k = 0; k < 16; k++) gacc[k] = 0.f;
        float sacc = 0.f;
        int ntile16 = (Nnew + 15) / 16;
        for (int t = blockIdx.x; t < ntile16; t += 256) {
            int r0 = t * 16;
            __syncthreads();
            for (int idx = tid; idx < 16 * 64; idx += 256) {
                int rr = idx >> 6, kk = idx & 63;
                int gr = r0 + rr;
                sx[idx] = (gr < Nnew) ? x[(size_t)gr * 64 + kk] : 0.f;
            }
            __syncthreads();
#pragma unroll 4
            for (int rr = 0; rr < 16; rr++) {
                float xj = sx[rr * 64 + j];
                if (tid < 64) sacc += xj;
#pragma unroll
                for (int k = 0; k < 16; k++)
                    gacc[k] += sx[rr * 64 + rg + 4 * k] * xj;
            }
        }
#pragma unroll
        for (int k = 0; k < 16; k++)
            atomicAdd(&g_G[(rg + 4 * k) * 64 + j], gacc[k]);
        if (tid < 64) atomicAdd(&g_s[tid], sacc);
    }

    __threadfence();
    __syncthreads();
    if (tid == 0) {
        int t = atomicAdd(&g_ticket, 1);
        s_last = (t == (int)gridDim.x - 1) ? 1 : 0;
    }
    __syncthreads();
    if (s_last) {
        for (int idx = tid; idx < 4096; idx += blockDim.x) {
            sG[idx] = g_G[idx];
            sW1s[idx] = W1[idx];
        }
        __syncthreads();
        if (tid < 64) {
            int c = tid;
            float invN = 1.f / (float)Nnew;
            float sdot = 0.f, q = 0.f;
            for (int ii = 0; ii < 64; ii++) {
                float wi = sW1s[c * 64 + ii];
                sdot += g_s[ii] * wi;
                float inner = 0.f;
                for (int jj = 0; jj < 64; jj++)
                    inner += sG[ii * 64 + jj] * sW1s[c * 64 + jj];
                q += wi * inner;
            }
            float bb = b1[c];
            float mu = sdot * invN + bb;
            float et2 = (q + 2.f * bb * sdot) * invN + bb * bb;
            float var = et2 - mu * mu;
            float a = gamma[c] * rsqrtf(var + 1e-5f);
            g_a[c] = a;
            g_bsh[c] = beta[c] - mu * a;
        }
        if (tid == 0) g_ticket = 0;
    }
}

// ---------------------------------------------------------------------------
// t12 + row-list build / selective zero / defaults. h written split.
// ---------------------------------------------------------------------------
__global__ void t12_kernel(const float* __restrict__ x,
                           const float* __restrict__ W1, const float* __restrict__ b1,
                           const float* __restrict__ W2, const float* __restrict__ b2,
                           float* __restrict__ out,
                           int Nnew, int Nold, int N) {
    __shared__ float sW1[64 * 65];
    __shared__ float sW2[64 * 65];
    __shared__ float sXT[32 * 64];
    __shared__ float sA[64], sB[64];
    int tid = threadIdx.x;
    int c = tid & 63, rg = tid >> 6;
    if (tid < 64) { sA[tid] = g_a[tid]; sB[tid] = g_bsh[tid]; }
    for (int idx = tid; idx < 64 * 64; idx += 256) {
        int j = idx >> 6, k = idx & 63;
        sW1[j * 65 + k] = W1[idx];
        sW2[j * 65 + k] = W2[idx];
    }
    int base = blockIdx.x * 32;
    for (int idx = tid; idx < 32 * 16; idx += 256) {
        int r = idx >> 4, k4 = idx & 15;
        int gr = base + r;
        float4 v = make_float4(0.f, 0.f, 0.f, 0.f);
        if (gr < Nnew) v = reinterpret_cast<const float4*>(x)[(size_t)gr * 16 + k4];
        reinterpret_cast<float4*>(sXT)[idx] = v;
    }
    __syncthreads();
    float acc[8];
    float bb = b1[c];
#pragma unroll
    for (int i = 0; i < 8; i++) acc[i] = bb;
#pragma unroll 4
    for (int k = 0; k < 64; k++) {
        float w = sW1[c * 65 + k];
#pragma unroll
        for (int i = 0; i < 8; i++) acc[i] += w * sXT[(rg * 8 + i) * 64 + k];
    }
    __syncthreads();
    float av = sA[c], bv = sB[c];
#pragma unroll
    for (int i = 0; i < 8; i++)
        sXT[(rg * 8 + i) * 64 + c] = fmaxf(fmaf(acc[i], av, bv), 0.f);
    __syncthreads();
    float acc2[8];
    float bb2 = b2[c];
#pragma unroll
    for (int i = 0; i < 8; i++) acc2[i] = bb2;
#pragma unroll 4
    for (int k = 0; k < 64; k++) {
        float w = sW2[c * 65 + k];
#pragma unroll
        for (int i = 0; i < 8; i++) acc2[i] += w * sXT[(rg * 8 + i) * 64 + k];
    }
#pragma unroll
    for (int i = 0; i < 8; i++) {
        int gr = base + rg * 8 + i;
        if (gr < Nnew) {
            int hr = Nold + gr;
            float val = g_dn[hr] * acc2[i];
            __nv_bfloat16 hi = __float2bfloat16(val);
            g_h_hi[(size_t)hr * 64 + c] = hi;
            g_h_lo[(size_t)hr * 64 + c] = __float2bfloat16(val - __bfloat162float(hi));
        }
    }

    {
        long long total_thr = (long long)gridDim.x * blockDim.x;
        long long gtid = (long long)blockIdx.x * blockDim.x + tid;
        int lane = tid & 31;
        float4 z4 = make_float4(0.f, 0.f, 0.f, 0.f);
        for (long long r = gtid; (r - lane) < N; r += total_thr) {
            bool act = r < N;
            float dnv = act ? g_dn[r] : 0.f;
            float dev = act ? g_de[r] : 0.f;
            bool fn = act && (dnv != 0.f);
            bool fe = act && (dev != 0.f);
            unsigned bn = __ballot_sync(0xffffffffu, fn);
            unsigned be = __ballot_sync(0xffffffffu, fe);
            int basen = 0, basee = 0;
            if (lane == 0) {
                if (bn) basen = atomicAdd(&g_ncnt, __popc(bn));
                if (be) basee = atomicAdd(&g_ecnt, __popc(be));
            }
            basen = __shfl_sync(0xffffffffu, basen, 0);
            basee = __shfl_sync(0xffffffffu, basee, 0);
            unsigned below = (1u << lane) - 1u;
            if (fn) {
                g_nlist[basen + __popc(bn & below)] = (int)r;
                float4* p = reinterpret_cast<float4*>(g_mn + (size_t)r * 64);
#pragma unroll
                for (int q = 0; q < 16; q++) p[q] = z4;
            }
            if (fe) {
                g_elist[basee + __popc(be & below)] = (int)r;
                float4* p = reinterpret_cast<float4*>(g_me + (size_t)r * 64);
#pragma unroll
                for (int q = 0; q < 16; q++) p[q] = z4;
            }
            if (act && !fn && !fe) {
                out[r] = 0.5f;
                out[N + r] = 0.f;
                float4* p = reinterpret_cast<float4*>(out + 2 * (size_t)N + (size_t)r * 64);
#pragma unroll
                for (int q = 0; q < 16; q++) p[q] = z4;
            }
        }
    }
    if (blockIdx.x == 0) {
        for (int idx = tid; idx < 4096; idx += 256) g_G[idx] = 0.f;
        if (tid < 64) g_s[tid] = 0.f;
    }
}

// ---------------------------------------------------------------------------
// SpMM with masked-row skip; h reconstructed from split hi/lo.
// ---------------------------------------------------------------------------
__global__ void spmm_kernel(const int* __restrict__ nrows, const int* __restrict__ ncols,
                            const float* __restrict__ nvals, int nnz_n,
                            const int* __restrict__ erows, const int* __restrict__ ecols,
                            const float* __restrict__ evals, int nnz_e) {
    long long gtid = (long long)blockIdx.x * blockDim.x + threadIdx.x;
    int q = (int)(gtid & 15);
    long long e = gtid >> 4;
    long long estride = ((long long)gridDim.x * blockDim.x) >> 4;
    long long total = (long long)nnz_n + nnz_e;
    for (; e < total; e += estride) {
        int r, cc; float v; float* m;
        if (e < nnz_n) {
            r = nrows[e]; cc = ncols[e];
            if (r == cc || __ldg(&g_dn[r]) == 0.f) continue;
            v = nvals[e]; m = g_mn;
        } else {
            long long e2 = e - nnz_n;
            r = erows[e2]; cc = ecols[e2];
            if (r == cc || __ldg(&g_de[r]) == 0.f) continue;
            v = evals[e2]; m = g_me;
        }
        uint2 a = __ldg(reinterpret_cast<const uint2*>(g_h_hi + (size_t)cc * 64 + q * 4));
        uint2 b = __ldg(reinterpret_cast<const uint2*>(g_h_lo + (size_t)cc * 64 + q * 4));
        float f0 = bfu_((unsigned short)(a.x & 0xffff)) + bfu_((unsigned short)(b.x & 0xffff));
        float f1 = bfu_((unsigned short)(a.x >> 16))    + bfu_((unsigned short)(b.x >> 16));
        float f2 = bfu_((unsigned short)(a.y & 0xffff)) + bfu_((unsigned short)(b.y & 0xffff));
        float f3 = bfu_((unsigned short)(a.y >> 16))    + bfu_((unsigned short)(b.y >> 16));
        float* mp = m + (size_t)r * 64 + q * 4;
        asm volatile("red.global.add.v4.f32 [%0], {%1, %2, %3, %4};"
                     :: "l"(mp), "f"(v * f0), "f"(v * f1), "f"(v * f2), "f"(v * f3)
                     : "memory");
    }
}

// ---------------------------------------------------------------------------
// GRU over a gathered row list. 512 threads, warp grid 4m x 4n.
// cp.async pipelining: m(t+1) raw fp32 -> SB_RAWM during tile t compute;
// h(t+1) split bf16 -> H operand buffers after combine(t) releases them.
// ---------------------------------------------------------------------------
#define WPAD 72
#define OPAD 68

#define SB_WIH 0
#define SB_WIL (SB_WIH + 192 * WPAD * 2)
#define SB_WHH (SB_WIL + 192 * WPAD * 2)
#define SB_WHL (SB_WHH + 192 * WPAD * 2)
#define SB_MHI (SB_WHL + 192 * WPAD * 2)
#define SB_MLO (SB_MHI + 128 * WPAD * 2)
#define SB_HHI (SB_MLO + 128 * WPAD * 2)
#define SB_HLO (SB_HHI + 128 * WPAD * 2)
#define SB_OUT SB_MHI   /* 128*68*4 = 34816 <= 36864 (M hi+lo region) */
#define SB_BIAS (SB_HLO + 128 * WPAD * 2)
#define SB_WY  (SB_BIAS + 4 * 64 * 4)
#define SB_DND (SB_WY + 512)
#define SB_Y   (SB_DND + 1024)
#define SB_IDX (SB_Y + 512)
#define SB_RAWM (SB_IDX + 512)          /* 128*64*4 = 32768 raw fp32 m stage */
#define SB_TOT (SB_RAWM + 32768)

#define GRU_THREADS 512

static __device__ __forceinline__ uint32_t smem_u32(const void* p) {
    uint32_t a;
    asm("{ .reg .u64 t; cvta.to.shared.u64 t, %1; cvt.u32.u64 %0, t; }" : "=r"(a) : "l"(p));
    return a;
}
static __device__ __forceinline__ void cpa16(uint32_t dst, const void* src, int sz) {
    asm volatile("cp.async.ca.shared.global [%0], [%1], 16, %2;"
                 :: "r"(dst), "l"(src), "r"(sz) : "memory");
}
static __device__ __forceinline__ void cpa_commit() {
    asm volatile("cp.async.commit_group;" ::: "memory");
}
static __device__ __forceinline__ void cpa_wait_all() {
    asm volatile("cp.async.wait_group 0;" ::: "memory");
}
static __device__ __forceinline__ void ldm_x4(uint32_t a[4], uint32_t addr) {
    asm volatile("ldmatrix.sync.aligned.m8n8.x4.shared.b16 {%0,%1,%2,%3}, [%4];"
                 : "=r"(a[0]), "=r"(a[1]), "=r"(a[2]), "=r"(a[3]) : "r"(addr));
}
static __device__ __forceinline__ void ldm_x2(uint32_t b[2], uint32_t addr) {
    asm volatile("ldmatrix.sync.aligned.m8n8.x2.shared.b16 {%0,%1}, [%2];"
                 : "=r"(b[0]), "=r"(b[1]) : "r"(addr));
}
static __device__ __forceinline__ void mma_bf16(float c[4], const uint32_t a[4], const uint32_t b[2]) {
    asm volatile("mma.sync.aligned.m16n8k16.row.col.f32.bf16.bf16.f32 "
                 "{%0,%1,%2,%3}, {%4,%5,%6,%7}, {%8,%9}, {%0,%1,%2,%3};"
                 : "+f"(c[0]), "+f"(c[1]), "+f"(c[2]), "+f"(c[3])
                 : "r"(a[0]), "r"(a[1]), "r"(a[2]), "r"(a[3]), "r"(b[0]), "r"(b[1]));
}
static __device__ __forceinline__ uint32_t a_addr(uint32_t base, int m0, int k0, int lane) {
    return base + (uint32_t)(((m0 + (lane & 15)) * WPAD + k0 + ((lane >> 4) << 3)) * 2);
}
static __device__ __forceinline__ uint32_t b_addr(uint32_t base, int n0, int k0, int lane) {
    int l = lane & 15;
    return base + (uint32_t)(((n0 + (l & 7)) * WPAD + k0 + ((l >> 3) << 3)) * 2);
}

static __device__ __forceinline__ void gate_mma(float C[2][2][4],
                                                const uint32_t ah[2][4], const uint32_t al[2][4],
                                                uint32_t sb, int bHi, int bLo,
                                                int ncol, int k0, int lane) {
#pragma unroll
    for (int ni = 0; ni < 2; ni++) {
        uint32_t bh[2], bl[2];
        ldm_x2(bh, b_addr(sb + bHi, ncol + ni * 8, k0, lane));
        ldm_x2(bl, b_addr(sb + bLo, ncol + ni * 8, k0, lane));
#pragma unroll
        for (int mi = 0; mi < 2; mi++) {
            mma_bf16(C[mi][ni], ah[mi], bh);
            mma_bf16(C[mi][ni], al[mi], bh);
            mma_bf16(C[mi][ni], ah[mi], bl);
        }
    }
}

// issue cp.async for tile tt's raw m rows (2048 x 16B)
static __device__ __forceinline__ void issue_m(uint32_t sb, const float* msrc,
                                               const int* list, int cnt, int tt, int tid) {
#pragma unroll
    for (int it = 0; it < 4; it++) {
        int idx = tid + it * GRU_THREADS;
        int row = idx >> 4, q = idx & 15;
        int li = tt * 128 + row;
        int gr = (li < cnt) ? __ldg(&list[li]) : -1;
        const float* src = msrc + (size_t)(gr < 0 ? 0 : gr) * 64 + q * 4;
        uint32_t dst = sb + SB_RAWM + (uint32_t)((row * 64 + q * 4) * 4);
        cpa16(dst, src, (gr >= 0) ? 16 : 0);
    }
}
// issue cp.async for tile tt's split h rows into H hi/lo buffers (2048 x 16B)
static __device__ __forceinline__ void issue_h(uint32_t sb, const int* list, int cnt,
                                               int tt, int tid) {
#pragma unroll
    for (int it = 0; it < 4; it++) {
        int idx = tid + it * GRU_THREADS;
        int row = idx >> 4;
        int rem = idx & 15;
        int part = rem >> 3, c = rem & 7;
        int li = tt * 128 + row;
        int gr = (li < cnt) ? __ldg(&list[li]) : -1;
        const __nv_bfloat16* base = part ? g_h_lo : g_h_hi;
        const void* src = base + (size_t)(gr < 0 ? 0 : gr) * 64 + c * 8;
        uint32_t dst = sb + (part ? SB_HLO : SB_HHI) + (uint32_t)((row * WPAD + c * 8) * 2);
        cpa16(dst, src, (gr >= 0) ? 16 : 0);
    }
}

__global__ void __launch_bounds__(GRU_THREADS, 1)
gru_kernel(int isEdge,
           const float* __restrict__ bi, const float* __restrict__ bh,
           const float* __restrict__ w_on, const float* __restrict__ b_on,
           const float* __restrict__ w_oe, const float* __restrict__ b_oe,
           float* __restrict__ out, int N) {
    extern __shared__ char sm[];
    uint32_t sb = smem_u32(sm);
    int tid = threadIdx.x;
    int lane = tid & 31, wid = tid >> 5;
    int mw = wid & 3, nw = wid >> 2;
    int m0w = mw * 32;
    int n0 = nw * 16;
    int g = lane >> 2, t = lane & 3;

    float* sBias = reinterpret_cast<float*>(sm + SB_BIAS);
    float* sWon = reinterpret_cast<float*>(sm + SB_WY);
    float* sWoe = sWon + 64;
    float* sDn = reinterpret_cast<float*>(sm + SB_DND);
    float* sDe = sDn + 128;
    float* sY = reinterpret_cast<float*>(sm + SB_Y);
    int* sIdx = reinterpret_cast<int*>(sm + SB_IDX);
    float* sOut = reinterpret_cast<float*>(sm + SB_OUT);
    float* sRaw = reinterpret_cast<float*>(sm + SB_RAWM);
    float* outH = out + 2 * (size_t)N;

    const int* list = isEdge ? g_elist : g_nlist;
    int cnt = isEdge ? g_ecnt : g_ncnt;
    const float* msrc = isEdge ? g_me : g_mn;
    int ntile = (cnt + 127) >> 7;

    // prologue: prefetch first tile's m and h
    if (blockIdx.x < ntile) {
        issue_m(sb, msrc, list, cnt, blockIdx.x, tid);
        issue_h(sb, list, cnt, blockIdx.x, tid);
    }
    cpa_commit();

    {
        const uint4* wih = reinterpret_cast<const uint4*>(g_wbh[isEdge * 2 + 0]);
        const uint4* wil = reinterpret_cast<const uint4*>(g_wbl[isEdge * 2 + 0]);
        const uint4* whh = reinterpret_cast<const uint4*>(g_wbh[isEdge * 2 + 1]);
        const uint4* whl = reinterpret_cast<const uint4*>(g_wbl[isEdge * 2 + 1]);
        for (int idx = tid; idx < 192 * 8; idx += GRU_THREADS) {
            int row = idx >> 3, q = idx & 7;
            int d = row * WPAD * 2 + q * 16;
            *reinterpret_cast<uint4*>(sm + SB_WIH + d) = wih[idx];
            *reinterpret_cast<uint4*>(sm + SB_WIL + d) = wil[idx];
            *reinterpret_cast<uint4*>(sm + SB_WHH + d) = whh[idx];
            *reinterpret_cast<uint4*>(sm + SB_WHL + d) = whl[idx];
        }
    }
    if (tid < 64) {
        sBias[tid]       = bi[tid] + bh[tid];
        sBias[64 + tid]  = bi[64 + tid] + bh[64 + tid];
        sBias[128 + tid] = bi[128 + tid];
        sBias[192 + tid] = bh[128 + tid];
        sWon[tid] = w_on[tid];
        sWoe[tid] = w_oe[tid];
    }

    for (int tile = blockIdx.x; tile < ntile; tile += gridDim.x) {
        cpa_wait_all();
        __syncthreads();   // copies visible to all + prev-tile readers done
        if (tid < 128) {
            int li = tile * 128 + tid;
            int gr = (li < cnt) ? list[li] : -1;
            sIdx[tid] = gr;
            sDn[tid] = (gr >= 0) ? g_dn[gr] : 0.f;
            sDe[tid] = (gr >= 0) ? g_de[gr] : 0.f;
            sY[tid] = 0.f;
        }
        // convert raw m (smem) -> bf16 hi/lo operand buffers
#pragma unroll
        for (int it = 0; it < 4; it++) {
            int idx = tid + it * GRU_THREADS;
            int row = idx >> 4, q = idx & 15;
            float4 v = *reinterpret_cast<float4*>(&sRaw[row * 64 + q * 4]);
            uint32_t hiw[2], low[2];
            cvt_pack(v, hiw, low);
            int d = (row * WPAD + q * 4) * 2;
            *reinterpret_cast<uint2*>(sm + SB_MHI + d) = make_uint2(hiw[0], hiw[1]);
            *reinterpret_cast<uint2*>(sm + SB_MLO + d) = make_uint2(low[0], low[1]);
        }
        __syncthreads();   // M bf16 + sIdx ready; sRaw consumed
        // prefetch next tile's m into sRaw (hidden behind MMA + combine)
        if (tile + (int)gridDim.x < ntile)
            issue_m(sb, msrc, list, cnt, tile + gridDim.x, tid);
        cpa_commit();

        float Cr[2][2][4], Cz[2][2][4], Ci[2][2][4], Ch[2][2][4];
#pragma unroll
        for (int a = 0; a < 2; a++)
#pragma unroll
            for (int b = 0; b < 2; b++)
#pragma unroll
                for (int c = 0; c < 4; c++) {
                    Cr[a][b][c] = 0.f; Cz[a][b][c] = 0.f;
                    Ci[a][b][c] = 0.f; Ch[a][b][c] = 0.f;
                }
#pragma unroll
        for (int k0 = 0; k0 < 64; k0 += 16) {
            uint32_t ah[2][4], al[2][4];
#pragma unroll
            for (int mi = 0; mi < 2; mi++) {
                ldm_x4(ah[mi], a_addr(sb + SB_MHI, m0w + mi * 16, k0, lane));
                ldm_x4(al[mi], a_addr(sb + SB_MLO, m0w + mi * 16, k0, lane));
            }
            gate_mma(Cr, ah, al, sb, SB_WIH, SB_WIL, 0 + n0, k0, lane);
            gate_mma(Cz, ah, al, sb, SB_WIH, SB_WIL, 64 + n0, k0, lane);
            gate_mma(Ci, ah, al, sb, SB_WIH, SB_WIL, 128 + n0, k0, lane);
        }
#pragma unroll
        for (int k0 = 0; k0 < 64; k0 += 16) {
            uint32_t ah[2][4], al[2][4];
#pragma unroll
            for (int mi = 0; mi < 2; mi++) {
                ldm_x4(ah[mi], a_addr(sb + SB_HHI, m0w + mi * 16, k0, lane));
                ldm_x4(al[mi], a_addr(sb + SB_HLO, m0w + mi * 16, k0, lane));
            }
            gate_mma(Cr, ah, al, sb, SB_WHH, SB_WHL, 0 + n0, k0, lane);
            gate_mma(Cz, ah, al, sb, SB_WHH, SB_WHL, 64 + n0, k0, lane);
            gate_mma(Ch, ah, al, sb, SB_WHH, SB_WHL, 128 + n0, k0, lane);
        }
        __syncthreads();   // M region dead -> sOut

        float ya[2][2] = {{0.f, 0.f}, {0.f, 0.f}};
#pragma unroll
        for (int mi = 0; mi < 2; mi++)
#pragma unroll
            for (int ni = 0; ni < 2; ni++)
#pragma unroll
                for (int rh = 0; rh < 2; rh++) {
                    int row = m0w + mi * 16 + g + rh * 8;
                    int colb = n0 + ni * 8 + 2 * t;
                    float dnv = sDn[row], dev = sDe[row];
                    float maskv = isEdge ? dev : dnv;
                    float cb[2];
#pragma unroll
                    for (int e = 0; e < 2; e++) {
                        int col = colb + e;
                        float rv = sigmoidf_(Cr[mi][ni][rh * 2 + e] + sBias[col]);
                        float zv = sigmoidf_(Cz[mi][ni][rh * 2 + e] + sBias[64 + col]);
                        float inv = Ci[mi][ni][rh * 2 + e] + sBias[128 + col];
                        float hnv = Ch[mi][ni][rh * 2 + e] + sBias[192 + col];
                        float ng = tanhf_(fmaf(rv, hnv, inv));
                        int hoff = (row * WPAD + col) * 2;
                        float hval = __bfloat162float(*reinterpret_cast<__nv_bfloat16*>(sm + SB_HHI + hoff)) +
                                     __bfloat162float(*reinterpret_cast<__nv_bfloat16*>(sm + SB_HLO + hoff));
                        cb[e] = maskv * fmaf(zv, hval - ng, ng);
                    }
                    *reinterpret_cast<float2*>(&sOut[row * OPAD + colb]) = make_float2(cb[0], cb[1]);
                    ya[mi][rh] += cb[0] * (dnv * sWon[colb] + dev * sWoe[colb]);
                    ya[mi][rh] += cb[1] * (dnv * sWon[colb + 1] + dev * sWoe[colb + 1]);
                }
#pragma unroll
        for (int mi = 0; mi < 2; mi++)
#pragma unroll
            for (int rh = 0; rh < 2; rh++) {
                ya[mi][rh] += __shfl_xor_sync(0xffffffffu, ya[mi][rh], 1);
                ya[mi][rh] += __shfl_xor_sync(0xffffffffu, ya[mi][rh], 2);
            }
        if (t == 0) {
#pragma unroll
            for (int mi = 0; mi < 2; mi++)
#pragma unroll
                for (int rh = 0; rh < 2; rh++)
                    atomicAdd(&sY[m0w + mi * 16 + g + rh * 8], ya[mi][rh]);
        }
        __syncthreads();   // H last read done (combine) -> prefetch next h

        if (tile + (int)gridDim.x < ntile)
            issue_h(sb, list, cnt, tile + gridDim.x, tid);
        cpa_commit();

        // coalesced h_out row stores + y epilogue
        for (int idx = tid; idx < 128 * 16; idx += GRU_THREADS) {
            int row = idx >> 4, q = idx & 15;
            int gr = sIdx[row];
            if (gr >= 0) {
                float4 v = *reinterpret_cast<float4*>(&sOut[row * OPAD + q * 4]);
                float4* hp = reinterpret_cast<float4*>(outH + (size_t)gr * 64 + q * 4);
                if (isEdge && sDn[row] != 0.f) {
                    float4 prev = *hp;
                    v.x += prev.x; v.y += prev.y; v.z += prev.z; v.w += prev.w;
                }
                *hp = v;
            }
        }
        if (tid < 128) {
            int gr = sIdx[tid];
            if (gr >= 0) {
                float dnv = sDn[tid], dev = sDe[tid];
                float ysum = sY[tid];
                if (!isEdge) {
                    float yv = ysum + dnv * b_on[0] + dev * b_oe[0];
                    out[N + gr] = yv;
                    if (dev == 0.f) out[gr] = sigmoidf_(yv);
                } else {
                    float yv;
                    if (dnv != 0.f) yv = out[N + gr] + ysum;
                    else yv = ysum + dev * b_oe[0];
                    out[N + gr] = yv;
                    out[gr] = sigmoidf_(yv);
                }
            }
        }
    }
}

// ---------------------------------------------------------------------------
extern "C" void kernel_launch(void* const* d_in, const int* in_sizes, int n_in,
                              void* d_out, int out_size) {
    const float* x     = (const float*)d_in[0];
    const float* h_in  = (const float*)d_in[1];
    const int*   nrows = (const int*)d_in[2];
    const int*   ncols = (const int*)d_in[3];
    const float* nvals = (const float*)d_in[4];
    const int*   erows = (const int*)d_in[5];
    const int*   ecols = (const int*)d_in[6];
    const float* evals = (const float*)d_in[7];
    const float* W1    = (const float*)d_in[8];
    const float* b1    = (const float*)d_in[9];
    const float* gamma = (const float*)d_in[10];
    const float* beta  = (const float*)d_in[11];
    const float* W2    = (const float*)d_in[12];
    const float* b2    = (const float*)d_in[13];
    const float* Wi_n  = (const float*)d_in[14];
    const float* bi_n  = (const float*)d_in[15];
    const float* Wh_n  = (const float*)d_in[16];
    const float* bh_n  = (const float*)d_in[17];
    const float* Wi_e  = (const float*)d_in[18];
    const float* bi_e  = (const float*)d_in[19];
    const float* Wh_e  = (const float*)d_in[20];
    const float* bh_e  = (const float*)d_in[21];
    const float* w_on  = (const float*)d_in[22];
    const float* b_on  = (const float*)d_in[23];
    const float* w_oe  = (const float*)d_in[24];
    const float* b_oe  = (const float*)d_in[25];

    int Nnew = in_sizes[0] / NH;
    int Nold = in_sizes[1] / NH;
    int N = Nnew + Nold;
    int nnz_n = in_sizes[2];
    int nnz_e = in_sizes[5];
    if (N > MAXN || Nnew > MAXNEW) return;

    float* out = (float*)d_out;

    cudaFuncSetAttribute(gru_kernel, cudaFuncAttributeMaxDynamicSharedMemorySize, SB_TOT);

    prep_kernel<<<2048, 256>>>(h_in, nrows, ncols, nvals, nnz_n,
                               erows, ecols, evals, nnz_e,
                               x, W1, b1, gamma, beta,
                               Wi_n, Wh_n, Wi_e, Wh_e, N, Nold, Nnew);
    t12_kernel<<<(Nnew + 31) / 32, 256>>>(x, W1, b1, W2, b2, out, Nnew, Nold, N);
    spmm_kernel<<<16384, 256>>>(nrows, ncols, nvals, nnz_n,
                                erows, ecols, evals, nnz_e);
    gru_kernel<<<148, GRU_THREADS, SB_TOT>>>(0, bi_n, bh_n, w_on, b_on, w_oe, b_oe, out, N);
    gru_kernel<<<148, GRU_THREADS, SB_TOT>>>(1, bi_e, bh_e, w_on, b_on, w_oe, b_oe, out, N);
    (void)n_in; (void)out_size;
}